// round 14
// baseline (speedup 1.0000x reference)
#include <cuda_runtime.h>
#include <cuda_fp16.h>
#include <cstdint>
#include <cstring>

#define SEQ   2048
#define DIM   1024
#define HEADS 16
#define DK    64
#define NSQ   ((size_t)SEQ * (size_t)SEQ)

// Scratch (device globals: allocation-free per harness rules)
__device__ __half g_qh[SEQ * DIM];
__device__ __half g_kh[SEQ * DIM];
__device__ __half g_vh[SEQ * DIM];
__device__ __half g_Wqh[DIM * DIM];
__device__ __half g_Wkh[DIM * DIM];
__device__ __half g_Wvh[DIM * DIM];
__device__ __half g_Woh[DIM * DIM];
__device__ __half g_Qp[SEQ * DIM];
__device__ __half g_Kp[SEQ * DIM];
__device__ __half g_VpT[DIM * SEQ];
__device__ __half g_ctxP[8][SEQ * DIM];   // per-j-block ctx partials
__device__ __half g_ctxM[SEQ * DIM];

// ---------------------------------------------------------------------------
__device__ __forceinline__ uint32_t h2_as_u32(__half2 h) {
    uint32_t u; memcpy(&u, &h, 4); return u;
}
__device__ __forceinline__ __half2 u32_as_h2(uint32_t u) {
    __half2 h; memcpy(&h, &u, 4); return h;
}
__device__ __forceinline__ uint32_t smem_u32(const void* p) {
    uint32_t a;
    asm("{ .reg .u64 t; cvta.to.shared.u64 t, %1; cvt.u32.u64 %0, t; }"
        : "=r"(a) : "l"(p));
    return a;
}
__device__ __forceinline__ void mma_f16(float c[4],
                                        const uint32_t a[4],
                                        const uint32_t b[2]) {
    asm volatile(
        "mma.sync.aligned.m16n8k16.row.col.f32.f16.f16.f32 "
        "{%0,%1,%2,%3}, {%4,%5,%6,%7}, {%8,%9}, {%0,%1,%2,%3};"
        : "+f"(c[0]), "+f"(c[1]), "+f"(c[2]), "+f"(c[3])
        : "r"(a[0]), "r"(a[1]), "r"(a[2]), "r"(a[3]),
          "r"(b[0]), "r"(b[1]));
}
__device__ __forceinline__ void ldsm_x4(uint32_t r[4], uint32_t addr) {
    asm volatile("ldmatrix.sync.aligned.m8n8.x4.shared.b16 {%0,%1,%2,%3}, [%4];"
                 : "=r"(r[0]), "=r"(r[1]), "=r"(r[2]), "=r"(r[3]) : "r"(addr));
}
__device__ __forceinline__ void ldsm_x2(uint32_t r[2], uint32_t addr) {
    asm volatile("ldmatrix.sync.aligned.m8n8.x2.shared.b16 {%0,%1}, [%2];"
                 : "=r"(r[0]), "=r"(r[1]) : "r"(addr));
}
#define CP16(dst_u32, src) \
    asm volatile("cp.async.cg.shared.global [%0], [%1], 16;" \
                 :: "r"(dst_u32), "l"(src) : "memory")
#define CP_COMMIT() asm volatile("cp.async.commit_group;" ::: "memory")
#define CP_WAIT(n)  asm volatile("cp.async.wait_group %0;" :: "n"(n) : "memory")

// ---------------------------------------------------------------------------
// Unified fp16 GEMM core (unchanged).
// ---------------------------------------------------------------------------
template <int BM, int BN, int WGM, bool TRANS, typename OutT>
__device__ __forceinline__ void gemm_pipe(
    const __half* __restrict__ A, size_t lda,
    const __half* __restrict__ B, size_t ldb,
    const float* __restrict__ bias,
    OutT* __restrict__ C, size_t ldc,
    int K, float scale, int m0, int n0)
{
    constexpr int KP = 40;
    constexpr int ASTAGE = BM * KP;
    constexpr int BSTAGE = BN * KP;
    constexpr int UNITS_A = BM * 4;
    constexpr int TOT = (BM + BN) * 4;
    constexpr int NU = (TOT + 255) / 256;
    constexpr int WGN = 8 / WGM;
    constexpr int MT = (BM / WGM) / 16;
    constexpr int NT = (BN / WGN) / 8;

    extern __shared__ char dynsmem[];
    __half* sA = (__half*)dynsmem;
    __half* sB = sA + 4 * ASTAGE;

    const int t    = threadIdx.x;
    const int w    = t >> 5;
    const int lane = t & 31;
    const int g    = lane >> 2;
    const int tig  = lane & 3;
    const int wm   = (w % WGM) * (BM / WGM);
    const int wn   = (w / WGM) * (BN / WGN);

    float acc[MT][NT][4];
    #pragma unroll
    for (int mt = 0; mt < MT; mt++)
        #pragma unroll
        for (int nt = 0; nt < NT; nt++)
            #pragma unroll
            for (int r = 0; r < 4; r++) acc[mt][nt][r] = 0.0f;

    const __half* Ab = A + (size_t)m0 * lda;
    const __half* Bb = B + (size_t)n0 * ldb;
    const uint32_t sAb = smem_u32(sA);
    const uint32_t sBb = smem_u32(sB);
    const int q = (t & 3) * 8;

    auto issue = [&](int c, int s) {
        const size_t kc = (size_t)c * 32;
        #pragma unroll
        for (int i = 0; i < NU; i++) {
            const int uid = t + i * 256;
            if (uid < UNITS_A) {
                const int row = uid >> 2;
                CP16(sAb + (uint32_t)(s * ASTAGE + row * KP + q) * 2,
                     Ab + (size_t)row * lda + kc + q);
            } else if (uid < TOT) {
                const int row = (uid - UNITS_A) >> 2;
                CP16(sBb + (uint32_t)(s * BSTAGE + row * KP + q) * 2,
                     Bb + (size_t)row * ldb + kc + q);
            }
        }
    };

    #pragma unroll
    for (int s = 0; s < 3; s++) { issue(s, s); CP_COMMIT(); }

    const int nc = K >> 5;
    for (int c = 0; c < nc; c++) {
        CP_WAIT(2);
        __syncthreads();
        const int buf = c & 3;
        const __half* cA = sA + (size_t)buf * ASTAGE;
        const __half* cB = sB + (size_t)buf * BSTAGE;
        #pragma unroll
        for (int kk = 0; kk < 2; kk++) {
            const int kc = kk * 16;
            uint32_t af[MT][4];
            #pragma unroll
            for (int mt = 0; mt < MT; mt++) {
                const int r = wm + mt * 16 + g;
                af[mt][0] = *(const uint32_t*)(cA + (size_t)r * KP + kc + 2 * tig);
                af[mt][1] = *(const uint32_t*)(cA + (size_t)(r + 8) * KP + kc + 2 * tig);
                af[mt][2] = *(const uint32_t*)(cA + (size_t)r * KP + kc + 2 * tig + 8);
                af[mt][3] = *(const uint32_t*)(cA + (size_t)(r + 8) * KP + kc + 2 * tig + 8);
            }
            uint32_t bf[NT][2];
            #pragma unroll
            for (int nt = 0; nt < NT; nt++) {
                const int col = wn + nt * 8 + g;
                bf[nt][0] = *(const uint32_t*)(cB + (size_t)col * KP + kc + 2 * tig);
                bf[nt][1] = *(const uint32_t*)(cB + (size_t)col * KP + kc + 2 * tig + 8);
            }
            #pragma unroll
            for (int mt = 0; mt < MT; mt++)
                #pragma unroll
                for (int nt = 0; nt < NT; nt++)
                    mma_f16(acc[mt][nt], af[mt], bf[nt]);
        }
        if (c + 3 < nc) issue(c + 3, (c + 3) & 3);
        CP_COMMIT();
    }

    #pragma unroll
    for (int mt = 0; mt < MT; mt++) {
        #pragma unroll
        for (int nt = 0; nt < NT; nt++) {
            const int row = m0 + wm + mt * 16 + g;
            const int col = n0 + wn + nt * 8 + tig * 2;
            const float b0 = bias ? bias[col]     : 0.0f;
            const float b1 = bias ? bias[col + 1] : 0.0f;
            const float v00 = acc[mt][nt][0] * scale + b0;
            const float v01 = acc[mt][nt][1] * scale + b1;
            const float v10 = acc[mt][nt][2] * scale + b0;
            const float v11 = acc[mt][nt][3] * scale + b1;
            if constexpr (!TRANS) {
                if constexpr (sizeof(OutT) == 4) {
                    *(float2*)((float*)C + (size_t)row * ldc + col)       = make_float2(v00, v01);
                    *(float2*)((float*)C + (size_t)(row + 8) * ldc + col) = make_float2(v10, v11);
                } else {
                    *(__half2*)((__half*)C + (size_t)row * ldc + col)       = __floats2half2_rn(v00, v01);
                    *(__half2*)((__half*)C + (size_t)(row + 8) * ldc + col) = __floats2half2_rn(v10, v11);
                }
            } else {
                C[(size_t)col * ldc + row]           = (OutT)v00;
                C[(size_t)(col + 1) * ldc + row]     = (OutT)v01;
                C[(size_t)col * ldc + row + 8]       = (OutT)v10;
                C[(size_t)(col + 1) * ldc + row + 8] = (OutT)v11;
            }
        }
    }
}

// ---------------------------------------------------------------------------
__global__ void __launch_bounds__(256)
k_cvt(const float* q, const float* k, const float* v,
      const float* Wq, const float* Wk, const float* Wv, const float* Wo)
{
    const float* src; __half* dst; int n;
    switch (blockIdx.z) {
        case 0: src = q;  dst = g_qh;  n = SEQ * DIM; break;
        case 1: src = k;  dst = g_kh;  n = SEQ * DIM; break;
        case 2: src = v;  dst = g_vh;  n = SEQ * DIM; break;
        case 3: src = Wq; dst = g_Wqh; n = DIM * DIM; break;
        case 4: src = Wk; dst = g_Wkh; n = DIM * DIM; break;
        case 5: src = Wv; dst = g_Wvh; n = DIM * DIM; break;
        default: src = Wo; dst = g_Woh; n = DIM * DIM; break;
    }
    const int idx = blockIdx.x * 256 + threadIdx.x;
    if (idx * 4 < n) {
        float4 f = *(const float4*)(src + idx * 4);
        uint2 o;
        ((__half2*)&o)[0] = __floats2half2_rn(f.x, f.y);
        ((__half2*)&o)[1] = __floats2half2_rn(f.z, f.w);
        *(uint2*)(dst + idx * 4) = o;
    }
}

__global__ void __launch_bounds__(256)
k_proj(const float* bq, const float* bk, const float* bv)
{
    const int m0 = blockIdx.y * 128, n0 = blockIdx.x * 128;
    if (blockIdx.z == 0)
        gemm_pipe<128, 128, 4, false, __half>(g_qh, DIM, g_Wqh, DIM, bq, g_Qp, DIM, DIM, 1.0f, m0, n0);
    else if (blockIdx.z == 1)
        gemm_pipe<128, 128, 4, false, __half>(g_kh, DIM, g_Wkh, DIM, bk, g_Kp, DIM, DIM, 1.0f, m0, n0);
    else
        gemm_pipe<128, 128, 4, true, __half>(g_vh, DIM, g_Wvh, DIM, bv, g_VpT, SEQ, DIM, 1.0f, m0, n0);
}

// ---------------------------------------------------------------------------
// Fused QK + heads-softmax + AV. ctx accumulators in packed fp16 (64 regs)
// to avoid the R13 register spill. Otherwise identical structure.
// ---------------------------------------------------------------------------
#define KPQ 1032
#define KPK 72
#define KSTG (64 * KPK)
#define WPITCH 72
#define WSTG (32 * WPITCH)

__global__ void __launch_bounds__(256, 1)
k_attn()
{
    extern __shared__ char dynsmem[];
    __half* sQ = (__half*)dynsmem;               // [32][KPQ]
    __half* sR = sQ + 32 * KPQ;                  // ring [4][64][KPK]
    __half* sW = sR + 4 * KSTG;                  // [2][32][WPITCH]

    const int t    = threadIdx.x;
    const int w    = t >> 5;
    const int lane = t & 31;
    const int g    = lane >> 2;
    const int tig  = lane & 3;
    const int wy   = (w & 1) * 16;
    const int wn   = (w >> 1) * 16;

    const int jb = blockIdx.x;
    const int i0 = blockIdx.y * 32;
    const int j0 = jb * 256;

    const uint32_t sQb = smem_u32(sQ);
    const uint32_t sRb = smem_u32(sR);
    const uint32_t sWb = smem_u32(sW);

    const int aRow  = wy + (lane & 7) + (lane & 8);
    const int aKoff = (lane & 16) ? 8 : 0;
    const uint32_t aBaseQ = sQb + (uint32_t)(aRow * KPQ + aKoff) * 2;
    const uint32_t aBaseW = (uint32_t)(aRow * WPITCH + aKoff) * 2;
    const int bRow  = (lane & 7);
    const int bKoff = (lane & 8) ? 8 : 0;

    #pragma unroll
    for (int i = 0; i < 16; i++) {
        const int uid = t + i * 256;
        const int row = uid >> 7;
        const int u   = uid & 127;
        CP16(sQb + (uint32_t)(row * KPQ + u * 8) * 2,
             g_Qp + (size_t)(i0 + row) * DIM + u * 8);
    }
    CP_COMMIT();

    auto issue_step = [&](int s) {
        if (s < 128) {
            const int jt2 = s >> 5;
            const int r   = s & 31;
            const uint32_t slotb = sRb + (uint32_t)((s & 3) * KSTG) * 2;
            if (r < 16) {
                #pragma unroll
                for (int i = 0; i < 2; i++) {
                    const int uid = t + i * 256;
                    const int row = uid >> 3;
                    const int u   = uid & 7;
                    CP16(slotb + (uint32_t)(row * KPK + u * 8) * 2,
                         g_Kp + (size_t)(j0 + jt2 * 64 + row) * DIM + r * 64 + u * 8);
                }
            } else {
                const int h = r - 16;
                #pragma unroll
                for (int i = 0; i < 2; i++) {
                    const int uid = t + i * 256;
                    const int row = uid >> 3;
                    const int u   = uid & 7;
                    CP16(slotb + (uint32_t)(row * KPK + u * 8) * 2,
                         g_VpT + (size_t)(h * 64 + row) * SEQ + j0 + jt2 * 64 + u * 8);
                }
            }
        }
    };
    #pragma unroll
    for (int s = 0; s < 3; s++) { issue_step(s); CP_COMMIT(); }

    const float scale = 0.125f;

    // ctx accumulators in packed fp16: [h][nt][rowhalf] (64 registers)
    uint32_t ctxh[HEADS][2][2];
    #pragma unroll
    for (int h = 0; h < HEADS; h++)
        #pragma unroll
        for (int nt = 0; nt < 2; nt++) {
            ctxh[h][nt][0] = 0u;
            ctxh[h][nt][1] = 0u;
        }

    #pragma unroll 1
    for (int jt = 0; jt < 4; jt++) {
        uint32_t sc[HEADS][4];
        float2 sum2[4];
        #pragma unroll
        for (int pp = 0; pp < 4; pp++) sum2[pp] = make_float2(0.f, 0.f);

        // ---- phase 1: QK for all heads
        #pragma unroll
        for (int h = 0; h < HEADS; h++) {
            const int step = jt * 32 + h;
            CP_WAIT(2);
            __syncthreads();
            const uint32_t kbuf = sRb + (uint32_t)((step & 3) * KSTG) * 2;

            float acc[2][4];
            #pragma unroll
            for (int nt = 0; nt < 2; nt++)
                #pragma unroll
                for (int r = 0; r < 4; r++) acc[nt][r] = 0.0f;

            const int kbase = h * 64;
            #pragma unroll
            for (int kk = 0; kk < 4; kk++) {
                const int kc = kk * 16;
                uint32_t af[4];
                ldsm_x4(af, aBaseQ + (uint32_t)(kbase + kc) * 2);
                #pragma unroll
                for (int nt = 0; nt < 2; nt++) {
                    uint32_t bf[2];
                    ldsm_x2(bf, kbuf +
                            (uint32_t)((wn + nt * 8 + bRow) * KPK + kc + bKoff) * 2);
                    mma_f16(acc[nt], af, bf);
                }
            }
            #pragma unroll
            for (int nt = 0; nt < 2; nt++) {
                float e0 = __expf(acc[nt][0] * scale);
                float e1 = __expf(acc[nt][1] * scale);
                float e2 = __expf(acc[nt][2] * scale);
                float e3 = __expf(acc[nt][3] * scale);
                sum2[nt * 2 + 0].x += e0; sum2[nt * 2 + 0].y += e1;
                sum2[nt * 2 + 1].x += e2; sum2[nt * 2 + 1].y += e3;
                sc[h][nt * 2 + 0] = h2_as_u32(__floats2half2_rn(e0, e1));
                sc[h][nt * 2 + 1] = h2_as_u32(__floats2half2_rn(e2, e3));
            }
            issue_step(step + 3);
            CP_COMMIT();
        }

        // ---- phase 2: denominators
        float2 inv[4];
        #pragma unroll
        for (int pp = 0; pp < 4; pp++)
            inv[pp] = make_float2(1.0f / sum2[pp].x, 1.0f / sum2[pp].y);

        // ---- phase 3: AV for all heads
        #pragma unroll
        for (int h = 0; h < HEADS; h++) {
            const int step = jt * 32 + 16 + h;
            CP_WAIT(2);
            __syncthreads();
            const uint32_t vbuf = sRb + (uint32_t)((step & 3) * KSTG) * 2;

            __half* stg = sW + (h & 1) * WSTG;
            #pragma unroll
            for (int nt = 0; nt < 2; nt++) {
                float2 f0 = __half22float2(u32_as_h2(sc[h][nt * 2 + 0]));
                float2 f1 = __half22float2(u32_as_h2(sc[h][nt * 2 + 1]));
                *(__half2*)(stg + (size_t)(wy + g) * WPITCH + wn + nt * 8 + 2 * tig) =
                    __floats2half2_rn(f0.x * inv[nt * 2].x, f0.y * inv[nt * 2].y);
                *(__half2*)(stg + (size_t)(wy + g + 8) * WPITCH + wn + nt * 8 + 2 * tig) =
                    __floats2half2_rn(f1.x * inv[nt * 2 + 1].x, f1.y * inv[nt * 2 + 1].y);
            }
            __syncthreads();

            const uint32_t aW = sWb + (uint32_t)((h & 1) * WSTG) * 2 + aBaseW;
            float acc[2][4];
            #pragma unroll
            for (int nt = 0; nt < 2; nt++)
                #pragma unroll
                for (int r = 0; r < 4; r++) acc[nt][r] = 0.0f;

            #pragma unroll
            for (int kk = 0; kk < 4; kk++) {
                const int kc = kk * 16;
                uint32_t af[4];
                ldsm_x4(af, aW + (uint32_t)kc * 2);
                #pragma unroll
                for (int nt = 0; nt < 2; nt++) {
                    uint32_t bf[2];
                    ldsm_x2(bf, vbuf +
                            (uint32_t)((wn + nt * 8 + bRow) * KPK + kc + bKoff) * 2);
                    mma_f16(acc[nt], af, bf);
                }
            }
            // accumulate into packed fp16 ctx
            #pragma unroll
            for (int nt = 0; nt < 2; nt++) {
                ctxh[h][nt][0] = h2_as_u32(__hadd2(u32_as_h2(ctxh[h][nt][0]),
                                       __floats2half2_rn(acc[nt][0], acc[nt][1])));
                ctxh[h][nt][1] = h2_as_u32(__hadd2(u32_as_h2(ctxh[h][nt][1]),
                                       __floats2half2_rn(acc[nt][2], acc[nt][3])));
            }
            issue_step(step + 3);
            CP_COMMIT();
        }
    }

    // ---- write ctx partial (fp16) to this j-block's buffer
    __half* outp = g_ctxP[jb];
    #pragma unroll
    for (int h = 0; h < HEADS; h++) {
        #pragma unroll
        for (int nt = 0; nt < 2; nt++) {
            const int row = i0 + wy + g;
            const int col = h * 64 + wn + nt * 8 + 2 * tig;
            *(__half2*)(outp + (size_t)row * DIM + col)       = u32_as_h2(ctxh[h][nt][0]);
            *(__half2*)(outp + (size_t)(row + 8) * DIM + col) = u32_as_h2(ctxh[h][nt][1]);
        }
    }
}

// ---------------------------------------------------------------------------
__global__ void __launch_bounds__(256)
k_merge8()
{
    const size_t idx = ((size_t)blockIdx.x * 256 + threadIdx.x) * 8;
    float acc[8];
    #pragma unroll
    for (int i = 0; i < 8; i++) acc[i] = 0.0f;
    #pragma unroll
    for (int p = 0; p < 8; p++) {
        uint4 u = *(const uint4*)(&g_ctxP[p][idx]);
        #pragma unroll
        for (int i = 0; i < 4; i++) {
            float2 f = __half22float2(((const __half2*)&u)[i]);
            acc[2 * i]     += f.x;
            acc[2 * i + 1] += f.y;
        }
    }
    uint4 o;
    #pragma unroll
    for (int i = 0; i < 4; i++)
        ((__half2*)&o)[i] = __floats2half2_rn(acc[2 * i], acc[2 * i + 1]);
    *(uint4*)(&g_ctxM[idx]) = o;
}

__global__ void __launch_bounds__(256)
k_out(const float* bo, float* out)
{
    gemm_pipe<32, 128, 1, false, float>(
        g_ctxM, DIM, g_Woh, DIM, bo, out, DIM, DIM, 1.0f,
        blockIdx.y * 32, blockIdx.x * 128);
}

// ---------------------------------------------------------------------------
static const int SMEM_P  = 4 * (128 + 128) * 40 * 2;              // 81920 B
static const int SMEM_O  = 4 * (32 + 128) * 40 * 2;               // 51200 B
static const int SMEM_AT = (32 * KPQ + 4 * KSTG + 2 * WSTG) * 2;  // 112128 B

extern "C" void kernel_launch(void* const* d_in, const int* in_sizes, int n_in,
                              void* d_out, int out_size)
{
    const float* q  = (const float*)d_in[0];
    const float* k  = (const float*)d_in[1];
    const float* v  = (const float*)d_in[2];
    const float* Wq = (const float*)d_in[3];
    const float* bq = (const float*)d_in[4];
    const float* Wk = (const float*)d_in[5];
    const float* bk = (const float*)d_in[6];
    const float* Wv = (const float*)d_in[7];
    const float* bv = (const float*)d_in[8];
    const float* Wo = (const float*)d_in[9];
    const float* bo = (const float*)d_in[10];
    float* out = (float*)d_out;

    static bool attr_done = false;
    if (!attr_done) {
        cudaFuncSetAttribute(k_proj, cudaFuncAttributeMaxDynamicSharedMemorySize, SMEM_P);
        cudaFuncSetAttribute(k_out,  cudaFuncAttributeMaxDynamicSharedMemorySize, SMEM_O);
        cudaFuncSetAttribute(k_attn, cudaFuncAttributeMaxDynamicSharedMemorySize, SMEM_AT);
        attr_done = true;
    }

    // 0) fp32 -> fp16 conversion
    k_cvt<<<dim3(SEQ * DIM / 4 / 256, 1, 7), 256>>>(q, k, v, Wq, Wk, Wv, Wo);

    // 1) Q/K/V projections
    k_proj<<<dim3(DIM / 128, SEQ / 128, 3), 256, SMEM_P>>>(bq, bk, bv);

    // 2) fused QK + heads-softmax + AV (fp16 ctx accumulators, no spills)
    k_attn<<<dim3(8, SEQ / 32), 256, SMEM_AT>>>();

    // 3) merge 8 j-block ctx partials
    k_merge8<<<SEQ * DIM / 8 / 256, 256>>>();

    // 4) output projection
    k_out<<<dim3(DIM / 128, SEQ / 32, 1), 256, SMEM_O>>>(bo, out);
}

// round 15
// speedup vs baseline: 1.1594x; 1.1594x over previous
#include <cuda_runtime.h>
#include <cuda_fp16.h>
#include <cstdint>
#include <cstring>

#define SEQ   2048
#define DIM   1024
#define HEADS 16
#define DK    64
#define NSQ   ((size_t)SEQ * (size_t)SEQ)

// Scratch (device globals: allocation-free per harness rules)
__device__ __half g_qh[SEQ * DIM];
__device__ __half g_kh[SEQ * DIM];
__device__ __half g_vh[SEQ * DIM];
__device__ __half g_Wqh[DIM * DIM];
__device__ __half g_Wkh[DIM * DIM];
__device__ __half g_Wvh[DIM * DIM];
__device__ __half g_Woh[DIM * DIM];
__device__ __half g_Qp[SEQ * DIM];
__device__ __half g_Kp[SEQ * DIM];
__device__ __half g_VpT[DIM * SEQ];
__device__ __half g_ctxA[SEQ * DIM];
__device__ __half g_ctxB[SEQ * DIM];
__device__ __half g_ctxC[SEQ * DIM];
__device__ __half g_ctxD[SEQ * DIM];
__device__ __half g_ctxM[SEQ * DIM];
__device__ __half g_att[(size_t)HEADS * SEQ * SEQ];

// ---------------------------------------------------------------------------
__device__ __forceinline__ uint32_t h2_as_u32(__half2 h) {
    uint32_t u; memcpy(&u, &h, 4); return u;
}
__device__ __forceinline__ __half2 u32_as_h2(uint32_t u) {
    __half2 h; memcpy(&h, &u, 4); return h;
}
__device__ __forceinline__ uint32_t smem_u32(const void* p) {
    uint32_t a;
    asm("{ .reg .u64 t; cvta.to.shared.u64 t, %1; cvt.u32.u64 %0, t; }"
        : "=r"(a) : "l"(p));
    return a;
}
__device__ __forceinline__ void mma_f16(float c[4],
                                        const uint32_t a[4],
                                        const uint32_t b[2]) {
    asm volatile(
        "mma.sync.aligned.m16n8k16.row.col.f32.f16.f16.f32 "
        "{%0,%1,%2,%3}, {%4,%5,%6,%7}, {%8,%9}, {%0,%1,%2,%3};"
        : "+f"(c[0]), "+f"(c[1]), "+f"(c[2]), "+f"(c[3])
        : "r"(a[0]), "r"(a[1]), "r"(a[2]), "r"(a[3]),
          "r"(b[0]), "r"(b[1]));
}
__device__ __forceinline__ void ldsm_x4(uint32_t r[4], uint32_t addr) {
    asm volatile("ldmatrix.sync.aligned.m8n8.x4.shared.b16 {%0,%1,%2,%3}, [%4];"
                 : "=r"(r[0]), "=r"(r[1]), "=r"(r[2]), "=r"(r[3]) : "r"(addr));
}
__device__ __forceinline__ void ldsm_x2(uint32_t r[2], uint32_t addr) {
    asm volatile("ldmatrix.sync.aligned.m8n8.x2.shared.b16 {%0,%1}, [%2];"
                 : "=r"(r[0]), "=r"(r[1]) : "r"(addr));
}
#define CP16(dst_u32, src) \
    asm volatile("cp.async.cg.shared.global [%0], [%1], 16;" \
                 :: "r"(dst_u32), "l"(src) : "memory")
#define CP_COMMIT() asm volatile("cp.async.commit_group;" ::: "memory")
#define CP_WAIT(n)  asm volatile("cp.async.wait_group %0;" :: "n"(n) : "memory")

// ---------------------------------------------------------------------------
// Unified fp16 GEMM core. R15: fragment loads via ldmatrix.
// A: MT x ldsm_x4 (matrices = {r k0, r+8 k0, r k8, r+8 k8}).
// B: NT/2 x ldsm_x4 over nt-pairs (matrices = {c k0, c k8, c+8 k0, c+8 k8}).
// KP=40 halves (80B rows) -> 8 rows hit 8 distinct 16B bank groups: conflict-free.
// ---------------------------------------------------------------------------
template <int BM, int BN, int WGM, bool TRANS, typename OutT>
__device__ __forceinline__ void gemm_pipe(
    const __half* __restrict__ A, size_t lda,
    const __half* __restrict__ B, size_t ldb,
    const float* __restrict__ bias,
    OutT* __restrict__ C, size_t ldc,
    int K, float scale, int m0, int n0)
{
    constexpr int KP = 40;
    constexpr int ASTAGE = BM * KP;
    constexpr int BSTAGE = BN * KP;
    constexpr int UNITS_A = BM * 4;
    constexpr int TOT = (BM + BN) * 4;
    constexpr int NU = (TOT + 255) / 256;
    constexpr int WGN = 8 / WGM;
    constexpr int MT = (BM / WGM) / 16;
    constexpr int NT = (BN / WGN) / 8;

    extern __shared__ char dynsmem[];
    __half* sA = (__half*)dynsmem;
    __half* sB = sA + 4 * ASTAGE;

    const int t    = threadIdx.x;
    const int w    = t >> 5;
    const int lane = t & 31;
    const int g    = lane >> 2;
    const int tig  = lane & 3;
    const int wm   = (w % WGM) * (BM / WGM);
    const int wn   = (w / WGM) * (BN / WGN);

    // ldmatrix per-lane address components
    const int aRowL = (lane & 7) + (lane & 8);          // 0..15
    const int aKL   = (lane & 16) ? 8 : 0;
    const int bColL = (lane & 7) + ((lane & 16) >> 1);  // 0..15
    const int bKL   = (lane & 8) ? 8 : 0;

    float acc[MT][NT][4];
    #pragma unroll
    for (int mt = 0; mt < MT; mt++)
        #pragma unroll
        for (int nt = 0; nt < NT; nt++)
            #pragma unroll
            for (int r = 0; r < 4; r++) acc[mt][nt][r] = 0.0f;

    const __half* Ab = A + (size_t)m0 * lda;
    const __half* Bb = B + (size_t)n0 * ldb;
    const uint32_t sAb = smem_u32(sA);
    const uint32_t sBb = smem_u32(sB);
    const int q = (t & 3) * 8;

    auto issue = [&](int c, int s) {
        const size_t kc = (size_t)c * 32;
        #pragma unroll
        for (int i = 0; i < NU; i++) {
            const int uid = t + i * 256;
            if (uid < UNITS_A) {
                const int row = uid >> 2;
                CP16(sAb + (uint32_t)(s * ASTAGE + row * KP + q) * 2,
                     Ab + (size_t)row * lda + kc + q);
            } else if (uid < TOT) {
                const int row = (uid - UNITS_A) >> 2;
                CP16(sBb + (uint32_t)(s * BSTAGE + row * KP + q) * 2,
                     Bb + (size_t)row * ldb + kc + q);
            }
        }
    };

    #pragma unroll
    for (int s = 0; s < 3; s++) { issue(s, s); CP_COMMIT(); }

    const int nc = K >> 5;
    for (int c = 0; c < nc; c++) {
        CP_WAIT(2);
        __syncthreads();
        const int buf = c & 3;
        const uint32_t cAb = sAb + (uint32_t)(buf * ASTAGE) * 2;
        const uint32_t cBb = sBb + (uint32_t)(buf * BSTAGE) * 2;
        #pragma unroll
        for (int kk = 0; kk < 2; kk++) {
            const int kc = kk * 16;
            uint32_t af[MT][4];
            #pragma unroll
            for (int mt = 0; mt < MT; mt++)
                ldsm_x4(af[mt], cAb +
                        (uint32_t)((wm + mt * 16 + aRowL) * KP + kc + aKL) * 2);
            uint32_t bf[NT][2];
            #pragma unroll
            for (int np = 0; np < NT / 2; np++) {
                uint32_t tmp[4];
                ldsm_x4(tmp, cBb +
                        (uint32_t)((wn + np * 16 + bColL) * KP + kc + bKL) * 2);
                bf[2 * np][0]     = tmp[0];
                bf[2 * np][1]     = tmp[1];
                bf[2 * np + 1][0] = tmp[2];
                bf[2 * np + 1][1] = tmp[3];
            }
            #pragma unroll
            for (int mt = 0; mt < MT; mt++)
                #pragma unroll
                for (int nt = 0; nt < NT; nt++)
                    mma_f16(acc[mt][nt], af[mt], bf[nt]);
        }
        if (c + 3 < nc) issue(c + 3, (c + 3) & 3);
        CP_COMMIT();
    }

    #pragma unroll
    for (int mt = 0; mt < MT; mt++) {
        #pragma unroll
        for (int nt = 0; nt < NT; nt++) {
            const int row = m0 + wm + mt * 16 + g;
            const int col = n0 + wn + nt * 8 + tig * 2;
            const float b0 = bias ? bias[col]     : 0.0f;
            const float b1 = bias ? bias[col + 1] : 0.0f;
            const float v00 = acc[mt][nt][0] * scale + b0;
            const float v01 = acc[mt][nt][1] * scale + b1;
            const float v10 = acc[mt][nt][2] * scale + b0;
            const float v11 = acc[mt][nt][3] * scale + b1;
            if constexpr (!TRANS) {
                if constexpr (sizeof(OutT) == 4) {
                    *(float2*)((float*)C + (size_t)row * ldc + col)       = make_float2(v00, v01);
                    *(float2*)((float*)C + (size_t)(row + 8) * ldc + col) = make_float2(v10, v11);
                } else {
                    *(__half2*)((__half*)C + (size_t)row * ldc + col)       = __floats2half2_rn(v00, v01);
                    *(__half2*)((__half*)C + (size_t)(row + 8) * ldc + col) = __floats2half2_rn(v10, v11);
                }
            } else {
                C[(size_t)col * ldc + row]           = (OutT)v00;
                C[(size_t)(col + 1) * ldc + row]     = (OutT)v01;
                C[(size_t)col * ldc + row + 8]       = (OutT)v10;
                C[(size_t)(col + 1) * ldc + row + 8] = (OutT)v11;
            }
        }
    }
}

// ---------------------------------------------------------------------------
__global__ void __launch_bounds__(256)
k_cvt(const float* q, const float* k, const float* v,
      const float* Wq, const float* Wk, const float* Wv, const float* Wo)
{
    const float* src; __half* dst; int n;
    switch (blockIdx.z) {
        case 0: src = q;  dst = g_qh;  n = SEQ * DIM; break;
        case 1: src = k;  dst = g_kh;  n = SEQ * DIM; break;
        case 2: src = v;  dst = g_vh;  n = SEQ * DIM; break;
        case 3: src = Wq; dst = g_Wqh; n = DIM * DIM; break;
        case 4: src = Wk; dst = g_Wkh; n = DIM * DIM; break;
        case 5: src = Wv; dst = g_Wvh; n = DIM * DIM; break;
        default: src = Wo; dst = g_Woh; n = DIM * DIM; break;
    }
    const int idx = blockIdx.x * 256 + threadIdx.x;
    if (idx * 4 < n) {
        float4 f = *(const float4*)(src + idx * 4);
        uint2 o;
        ((__half2*)&o)[0] = __floats2half2_rn(f.x, f.y);
        ((__half2*)&o)[1] = __floats2half2_rn(f.z, f.w);
        *(uint2*)(dst + idx * 4) = o;
    }
}

__global__ void __launch_bounds__(256)
k_proj(const float* bq, const float* bk, const float* bv)
{
    const int m0 = blockIdx.y * 128, n0 = blockIdx.x * 128;
    if (blockIdx.z == 0)
        gemm_pipe<128, 128, 4, false, __half>(g_qh, DIM, g_Wqh, DIM, bq, g_Qp, DIM, DIM, 1.0f, m0, n0);
    else if (blockIdx.z == 1)
        gemm_pipe<128, 128, 4, false, __half>(g_kh, DIM, g_Wkh, DIM, bk, g_Kp, DIM, DIM, 1.0f, m0, n0);
    else
        gemm_pipe<128, 128, 4, true, __half>(g_vh, DIM, g_Wvh, DIM, bv, g_VpT, SEQ, DIM, 1.0f, m0, n0);
}

// ---------------------------------------------------------------------------
// Fused QK + heads-softmax (R12-proven: inline exp + ldmatrix + staged writes)
// ---------------------------------------------------------------------------
#define KPQ 1032
#define KPK 72
#define KSTG (64 * KPK)
#define WPITCH 72
#define WSTG (32 * WPITCH)

__global__ void __launch_bounds__(256)
k_qksm()
{
    extern __shared__ char dynsmem[];
    __half* sQ = (__half*)dynsmem;               // [32][KPQ]
    __half* sK = sQ + 32 * KPQ;                  // [4][64][KPK]
    __half* sW = sK + 4 * KSTG;                  // [2][32][WPITCH]

    const int t    = threadIdx.x;
    const int w    = t >> 5;
    const int lane = t & 31;
    const int g    = lane >> 2;
    const int tig  = lane & 3;
    const int wy   = (w & 1) * 16;
    const int wn   = (w >> 1) * 16;

    const int i0 = blockIdx.y * 32;
    const int j0 = blockIdx.x * 256;

    const uint32_t sQb = smem_u32(sQ);
    const uint32_t sKb = smem_u32(sK);

    const int aRow  = wy + (lane & 7) + (lane & 8);
    const int aKoff = (lane & 16) ? 8 : 0;
    const uint32_t aBase = sQb + (uint32_t)(aRow * KPQ + aKoff) * 2;
    const int bRow  = (lane & 7);
    const int bKoff = (lane & 8) ? 8 : 0;

    #pragma unroll
    for (int i = 0; i < 16; i++) {
        const int uid = t + i * 256;
        const int row = uid >> 7;
        const int u   = uid & 127;
        CP16(sQb + (uint32_t)(row * KPQ + u * 8) * 2,
             g_Qp + (size_t)(i0 + row) * DIM + u * 8);
    }
    CP_COMMIT();

    auto issueK = [&](int it, int s) {
        const int jt = it >> 4;
        const int h  = it & 15;
        #pragma unroll
        for (int i = 0; i < 2; i++) {
            const int uid = t + i * 256;
            const int row = uid >> 3;
            const int u   = uid & 7;
            CP16(sKb + (uint32_t)(s * KSTG + row * KPK + u * 8) * 2,
                 g_Kp + (size_t)(j0 + jt * 64 + row) * DIM + h * 64 + u * 8);
        }
    };
    #pragma unroll
    for (int s = 0; s < 3; s++) { issueK(s, s); CP_COMMIT(); }

    const float scale = 0.125f;
    const int r_ = t >> 3;
    const int o_ = t & 7;

    for (int jt = 0; jt < 4; jt++) {
        uint32_t sc[HEADS][4];          // packed exp values
        float2 sum2[4];
        #pragma unroll
        for (int pp = 0; pp < 4; pp++) sum2[pp] = make_float2(0.f, 0.f);

        #pragma unroll
        for (int h = 0; h < HEADS; h++) {
            const int it = jt * 16 + h;
            CP_WAIT(2);
            __syncthreads();
            const uint32_t sKbuf = sKb + (uint32_t)((it & 3) * KSTG) * 2;

            float acc[2][4];
            #pragma unroll
            for (int nt = 0; nt < 2; nt++)
                #pragma unroll
                for (int r = 0; r < 4; r++) acc[nt][r] = 0.0f;

            const int kbase = h * 64;
            #pragma unroll
            for (int kk = 0; kk < 4; kk++) {
                const int kc = kk * 16;
                uint32_t af[4];
                ldsm_x4(af, aBase + (uint32_t)(kbase + kc) * 2);
                #pragma unroll
                for (int nt = 0; nt < 2; nt++) {
                    uint32_t bf[2];
                    ldsm_x2(bf, sKbuf +
                            (uint32_t)((wn + nt * 8 + bRow) * KPK + kc + bKoff) * 2);
                    mma_f16(acc[nt], af, bf);
                }
            }
            #pragma unroll
            for (int nt = 0; nt < 2; nt++) {
                float e0 = __expf(acc[nt][0] * scale);
                float e1 = __expf(acc[nt][1] * scale);
                float e2 = __expf(acc[nt][2] * scale);
                float e3 = __expf(acc[nt][3] * scale);
                sum2[nt * 2 + 0].x += e0; sum2[nt * 2 + 0].y += e1;
                sum2[nt * 2 + 1].x += e2; sum2[nt * 2 + 1].y += e3;
                sc[h][nt * 2 + 0] = h2_as_u32(__floats2half2_rn(e0, e1));
                sc[h][nt * 2 + 1] = h2_as_u32(__floats2half2_rn(e2, e3));
            }
            if (it + 3 < 64) issueK(it + 3, (it + 3) & 3);
            CP_COMMIT();
        }

        float2 inv[4];
        #pragma unroll
        for (int pp = 0; pp < 4; pp++)
            inv[pp] = make_float2(1.0f / sum2[pp].x, 1.0f / sum2[pp].y);

        #pragma unroll
        for (int h = 0; h < HEADS; h++) {
            __half* stg = sW + (h & 1) * WSTG;
            #pragma unroll
            for (int nt = 0; nt < 2; nt++) {
                float2 f0 = __half22float2(u32_as_h2(sc[h][nt * 2 + 0]));
                float2 f1 = __half22float2(u32_as_h2(sc[h][nt * 2 + 1]));
                *(__half2*)(stg + (size_t)(wy + g) * WPITCH + wn + nt * 8 + 2 * tig) =
                    __floats2half2_rn(f0.x * inv[nt * 2].x, f0.y * inv[nt * 2].y);
                *(__half2*)(stg + (size_t)(wy + g + 8) * WPITCH + wn + nt * 8 + 2 * tig) =
                    __floats2half2_rn(f1.x * inv[nt * 2 + 1].x, f1.y * inv[nt * 2 + 1].y);
            }
            __syncthreads();
            uint4 val = *(const uint4*)(stg + (size_t)r_ * WPITCH + o_ * 8);
            *(uint4*)(g_att + (size_t)h * NSQ + (size_t)(i0 + r_) * SEQ
                      + j0 + jt * 64 + o_ * 8) = val;
        }
    }
}

// ---------------------------------------------------------------------------
__global__ void __launch_bounds__(256)
k_av()
{
    const int ks = blockIdx.x;
    const int m0 = blockIdx.y * 128;
    const int h  = blockIdx.z;
    __half* outp;
    switch (ks) {
        case 0:  outp = g_ctxA; break;
        case 1:  outp = g_ctxB; break;
        case 2:  outp = g_ctxC; break;
        default: outp = g_ctxD; break;
    }
    gemm_pipe<128, 64, 4, false, __half>(
        g_att + (size_t)h * NSQ + (size_t)ks * 512, SEQ,
        g_VpT + (size_t)(h * DK) * SEQ + (size_t)ks * 512, SEQ,
        nullptr,
        outp + h * DK, DIM,
        512, 1.0f, m0, 0);
}

__global__ void __launch_bounds__(256)
k_merge()
{
    const int idx = blockIdx.x * 256 + threadIdx.x;
    uint4 a = *(const uint4*)(g_ctxA + (size_t)idx * 8);
    uint4 b = *(const uint4*)(g_ctxB + (size_t)idx * 8);
    uint4 c = *(const uint4*)(g_ctxC + (size_t)idx * 8);
    uint4 d = *(const uint4*)(g_ctxD + (size_t)idx * 8);
    uint4 o;
    #pragma unroll
    for (int i = 0; i < 4; i++) {
        float2 fa = __half22float2(((const __half2*)&a)[i]);
        float2 fb = __half22float2(((const __half2*)&b)[i]);
        float2 fc = __half22float2(((const __half2*)&c)[i]);
        float2 fd = __half22float2(((const __half2*)&d)[i]);
        ((__half2*)&o)[i] = __floats2half2_rn(fa.x + fb.x + fc.x + fd.x,
                                              fa.y + fb.y + fc.y + fd.y);
    }
    *(uint4*)(&g_ctxM[(size_t)idx * 8]) = o;
}

__global__ void __launch_bounds__(256)
k_out(const float* bo, float* out)
{
    gemm_pipe<32, 128, 1, false, float>(
        g_ctxM, DIM, g_Woh, DIM, bo, out, DIM, DIM, 1.0f,
        blockIdx.y * 32, blockIdx.x * 128);
}

// ---------------------------------------------------------------------------
static const int SMEM_P  = 4 * (128 + 128) * 40 * 2;              // 81920 B
static const int SMEM_AV = 4 * (128 + 64) * 40 * 2;               // 61440 B
static const int SMEM_O  = 4 * (32 + 128) * 40 * 2;               // 51200 B
static const int SMEM_QS = (32 * KPQ + 4 * KSTG + 2 * WSTG) * 2;  // 112128 B

extern "C" void kernel_launch(void* const* d_in, const int* in_sizes, int n_in,
                              void* d_out, int out_size)
{
    const float* q  = (const float*)d_in[0];
    const float* k  = (const float*)d_in[1];
    const float* v  = (const float*)d_in[2];
    const float* Wq = (const float*)d_in[3];
    const float* bq = (const float*)d_in[4];
    const float* Wk = (const float*)d_in[5];
    const float* bk = (const float*)d_in[6];
    const float* Wv = (const float*)d_in[7];
    const float* bv = (const float*)d_in[8];
    const float* Wo = (const float*)d_in[9];
    const float* bo = (const float*)d_in[10];
    float* out = (float*)d_out;

    static bool attr_done = false;
    if (!attr_done) {
        cudaFuncSetAttribute(k_proj, cudaFuncAttributeMaxDynamicSharedMemorySize, SMEM_P);
        cudaFuncSetAttribute(k_av,   cudaFuncAttributeMaxDynamicSharedMemorySize, SMEM_AV);
        cudaFuncSetAttribute(k_out,  cudaFuncAttributeMaxDynamicSharedMemorySize, SMEM_O);
        cudaFuncSetAttribute(k_qksm, cudaFuncAttributeMaxDynamicSharedMemorySize, SMEM_QS);
        attr_done = true;
    }

    // 0) fp32 -> fp16 conversion
    k_cvt<<<dim3(SEQ * DIM / 4 / 256, 1, 7), 256>>>(q, k, v, Wq, Wk, Wv, Wo);

    // 1) Q/K/V projections
    k_proj<<<dim3(DIM / 128, SEQ / 128, 3), 256, SMEM_P>>>(bq, bk, bv);

    // 2) fused QK + heads-softmax
    k_qksm<<<dim3(SEQ / 256, SEQ / 32), 256, SMEM_QS>>>();

    // 3) attn @ V (K-split x4)
    k_av<<<dim3(4, SEQ / 128, HEADS), 256, SMEM_AV>>>();

    // 4) merge ctx partials
    k_merge<<<SEQ * DIM / 8 / 256, 256>>>();

    // 5) output projection
    k_out<<<dim3(DIM / 128, SEQ / 32, 1), 256, SMEM_O>>>(bo, out);
}